// round 6
// baseline (speedup 1.0000x reference)
#include <cuda_runtime.h>
#include <cstdint>
#include <cstring>
#include <cstdio>
#include <cstdlib>

#define WC 48
#define NCELL (48*48*48)
#define TFULL 96
#define TTRI 48
#define OS_A 117649
#define OS_X 2401
#define OS_Y 49
#define BT 64                       // threads per k_field block (2 cells/thread)
#define CPB 128                     // cells per block
#define STR 130                     // smem row stride (floats): 520 B, 8B-aligned

typedef unsigned long long u64;

struct Params {
    u64      cf[TTRI * 16];   // per-tri 15 packed-dup coeffs (+pad): see order below
    uint32_t epk[TTRI];       // e0 | e1<<8 | e2<<16
    uint32_t slotpack[24];    // col-group g: byte k = slot of col 4g+k (0xFF unused)
};
// cf order per tri: 0..2 c1xyz, 3..5 c2xyz, 6..8 g0xyz(=-h0), 9..11 h1xyz, 12..14 h2xyz

__device__ float4 g_sm[NCELL];

// ---- f32x2 packed helpers ----
__device__ __forceinline__ u64 fma2(u64 a, u64 b, u64 c) {
    u64 d; asm("fma.rn.f32x2 %0,%1,%2,%3;" : "=l"(d) : "l"(a), "l"(b), "l"(c)); return d;
}
__device__ __forceinline__ u64 mul2(u64 a, u64 b) {
    u64 d; asm("mul.rn.f32x2 %0,%1,%2;" : "=l"(d) : "l"(a), "l"(b)); return d;
}
__device__ __forceinline__ u64 add2(u64 a, u64 b) {
    u64 d; asm("add.rn.f32x2 %0,%1,%2;" : "=l"(d) : "l"(a), "l"(b)); return d;
}
__device__ __forceinline__ u64 neg2(u64 a) { return a ^ 0x8000000080000000ULL; }
__device__ __forceinline__ void unpk(u64 v, float& lo, float& hi) {
    uint32_t l, h; asm("mov.b64 {%0,%1},%2;" : "=r"(l), "=r"(h) : "l"(v));
    lo = __uint_as_float(l); hi = __uint_as_float(h);
}
__device__ __forceinline__ u64 pk2(float lo, float hi) {
    u64 v; asm("mov.b64 %0,{%1,%2};" : "=l"(v) : "f"(lo), "f"(hi)); return v;
}

// ---------------------------------------------------------------------------
// k_field: 2 cells/thread, packed f32x2 math, coeffs in smem (no in-loop LDC)
// ---------------------------------------------------------------------------
__global__ __launch_bounds__(BT) void k_field(
    const float* __restrict__ off, const float* __restrict__ topo,
    float* __restrict__ out, Params P)
{
    __shared__ float    st2[TTRI][STR];   // topology, column-major [slot][cell]
    __shared__ float    sd2[12][STR];     // displacements, column-major [edge][cell]
    __shared__ u64      scf[TTRI * 16];   // packed-dup coefficients
    __shared__ uint32_t sep[TTRI];        // epk
    __shared__ uint32_t ssl[24];          // slot map

    const int tid   = threadIdx.x;
    const int cell0 = blockIdx.x * CPB;
    const int t2    = 2 * tid;

    // copy tables to smem
    #pragma unroll
    for (int i = tid; i < TTRI * 16; i += BT) scf[i] = P.cf[i];
    if (tid < TTRI) sep[tid] = P.epk[tid];
    if (tid < 24)   ssl[tid] = P.slotpack[tid];
    if (cell0 == 0 && tid == 0) out[0] = 0.0f;

    // displacements for cells (c, c+1): z even, pair never straddles a row
    const int c = cell0 + t2;
    const int z = c % WC, y = (c / WC) % WC, x = c / (WC * WC);
    const float* ob = off + x * OS_X + y * OS_Y + z;
    const int O[12] = {0, OS_Y, 1, OS_Y + 1,
                       OS_A, OS_A + OS_X, OS_A + 1, OS_A + OS_X + 1,
                       2*OS_A, 2*OS_A + OS_X, 2*OS_A + OS_Y, 2*OS_A + OS_X + OS_Y};
    #pragma unroll
    for (int e = 0; e < 12; ++e)
        *reinterpret_cast<float2*>(&sd2[e][t2]) = make_float2(ob[O[e]], ob[O[e] + 1]);

    __syncthreads();   // ssl visible

    // stage topology: coalesced float4 loads, scatter needed cols to st2[slot][cell]
    const float4* t4 = reinterpret_cast<const float4*>(topo) + (size_t)cell0 * 24;
    #pragma unroll
    for (int it = 0; it < 48; ++it) {
        int i = tid + it * BT;            // [0, 3072)
        float4 v = t4[i];
        int r = i / 24, g = i % 24;
        uint32_t sp = ssl[g];
        uint32_t s0 = sp & 0xffu, s1 = (sp >> 8) & 0xffu,
                 s2v = (sp >> 16) & 0xffu, s3 = sp >> 24;
        if (s0  != 0xffu) st2[s0][r]  = v.x;
        if (s1  != 0xffu) st2[s1][r]  = v.y;
        if (s2v != 0xffu) st2[s2v][r] = v.z;
        if (s3  != 0xffu) st2[s3][r]  = v.w;
    }

    __syncthreads();

    const u64 EPS2 = 0x322BCC77322BCC77ULL;   // (1e-8f, 1e-8f)
    u64 s2 = 0, mx2 = 0, my2 = 0, mz2 = 0;
    #pragma unroll 8
    for (int t = 0; t < TTRI; ++t) {
        const u64* C = &scf[t * 16];          // uniform smem broadcast
        uint32_t e = sep[t];
        u64 d0 = *reinterpret_cast<const u64*>(&sd2[e & 0xffu][t2]);
        u64 d1 = *reinterpret_cast<const u64*>(&sd2[(e >> 8) & 0xffu][t2]);
        u64 d2 = *reinterpret_cast<const u64*>(&sd2[(e >> 16) & 0xffu][t2]);
        u64 p  = *reinterpret_cast<const u64*>(&st2[t][t2]);
        u64 ax = fma2(d1, C[9],  fma2(d0, C[6], C[0]));
        u64 ay = fma2(d1, C[10], fma2(d0, C[7], C[1]));
        u64 az = fma2(d1, C[11], fma2(d0, C[8], C[2]));
        u64 bx = fma2(d2, C[12], fma2(d0, C[6], C[3]));
        u64 by = fma2(d2, C[13], fma2(d0, C[7], C[4]));
        u64 bz = fma2(d2, C[14], fma2(d0, C[8], C[5]));
        u64 nx = fma2(ay, bz, neg2(mul2(az, by)));
        u64 ny = fma2(az, bx, neg2(mul2(ax, bz)));
        u64 nz = fma2(ax, by, neg2(mul2(ay, bx)));
        u64 nn = fma2(nx, nx, fma2(ny, ny, fma2(nz, nz, EPS2)));
        float nlo, nhi; unpk(nn, nlo, nhi);
        u64 inv = pk2(rsqrtf(nlo), rsqrtf(nhi));
        s2 = add2(s2, p);
        u64 w = mul2(p, inv);
        mx2 = fma2(w, nx, mx2); my2 = fma2(w, ny, my2); mz2 = fma2(w, nz, mz2);
    }

    float sl, sh, xl, xh, yl, yh, zl, zh;
    unpk(s2, sl, sh); unpk(mx2, xl, xh); unpk(my2, yl, yh); unpk(mz2, zl, zh);
    g_sm[c]     = make_float4(sl, xl, yl, zl);
    g_sm[c + 1] = make_float4(sh, xh, yh, zh);
}

// ---------------------------------------------------------------------------
// k_pair: self + forward-neighbor terms; float atomic into out[0]
// ---------------------------------------------------------------------------
__global__ __launch_bounds__(256) void k_pair(float* __restrict__ out)
{
    int c = blockIdx.x * 256 + threadIdx.x;
    int z = c % WC, xy = c / WC, y = xy % WC, x = xy / WC;
    float4 a = g_sm[c];
    float acc = a.x*a.x - a.y*a.y - a.z*a.z - a.w*a.w;
    if (x < WC-1) { float4 b = g_sm[c + WC*WC]; acc += a.x*b.x - a.y*b.y - a.z*b.z - a.w*b.w; }
    if (y < WC-1) { float4 b = g_sm[c + WC];    acc += a.x*b.x - a.y*b.y - a.z*b.z - a.w*b.w; }
    if (z < WC-1) { float4 b = g_sm[c + 1];     acc += a.x*b.x - a.y*b.y - a.z*b.z - a.w*b.w; }
    acc *= 2.0f;
    #pragma unroll
    for (int o = 16; o > 0; o >>= 1) acc += __shfl_down_sync(0xffffffffu, acc, o);
    __shared__ float red[8];
    if ((threadIdx.x & 31) == 0) red[threadIdx.x >> 5] = acc;
    __syncthreads();
    if (threadIdx.x < 8) {
        float v = red[threadIdx.x];
        #pragma unroll
        for (int o = 4; o > 0; o >>= 1) v += __shfl_down_sync(0xffu, v, o);
        if (threadIdx.x == 0) atomicAdd(out, v);
    }
}

// ---------------------------------------------------------------------------
// HOST: geometry + params
// ---------------------------------------------------------------------------
static const int EC[12][3] = {{0,0,0},{0,1,0},{0,0,1},{0,1,1},
                              {0,0,0},{1,0,0},{0,0,1},{1,0,1},
                              {0,0,0},{1,0,0},{0,1,0},{1,1,0}};
static const int EA[12] = {0,0,0,0,1,1,1,1,2,2,2,2};

static u64 dupf(float f) { uint32_t b; memcpy(&b, &f, 4); return (u64)b | ((u64)b << 32); }

static void make_params(const int tri[TTRI][3], const int cols[TTRI], Params* P)
{
    for (int t = 0; t < TTRI; ++t) {
        int e0 = tri[t][0], e1 = tri[t][1], e2 = tri[t][2];
        float b0[3], b1[3], b2[3];
        for (int k = 0; k < 3; ++k) {
            b0[k] = EC[e0][k] + (k == EA[e0] ? 0.5f : 0.f);
            b1[k] = EC[e1][k] + (k == EA[e1] ? 0.5f : 0.f);
            b2[k] = EC[e2][k] + (k == EA[e2] ? 0.5f : 0.f);
        }
        u64* C = &P->cf[t * 16];
        for (int k = 0; k < 3; ++k) {
            C[0 + k]  = dupf(b1[k] - b0[k]);            // c1
            C[3 + k]  = dupf(b2[k] - b0[k]);            // c2
            C[6 + k]  = dupf(-(float)(EA[e0] == k));    // g0 = -h0
            C[9 + k]  = dupf((float)(EA[e1] == k));     // h1
            C[12 + k] = dupf((float)(EA[e2] == k));     // h2
        }
        C[15] = 0;
        P->epk[t] = (uint32_t)e0 | ((uint32_t)e1 << 8) | ((uint32_t)e2 << 16);
    }
    for (int g = 0; g < 24; ++g) {
        uint32_t sp = 0;
        for (int k = 0; k < 4; ++k) {
            int col = 4*g + k, slot = 0xFF;
            for (int s = 0; s < TTRI; ++s) if (cols[s] == col) { slot = s; break; }
            sp |= (uint32_t)slot << (8*k);
        }
        P->slotpack[g] = sp;
    }
}

// ---- ground-truth tables from in-container python/numpy (verified working) ----
static const char* PY_CMD =
    "python3 -c 'import numpy as np;r=np.random.default_rng(0);"
    "a=[r.choice(12,size=3,replace=False) for _ in range(48)];"
    "b=np.sort(r.choice(96,size=48,replace=False));"
    "print(\"TRI=\"+\",\".join(str(int(v)) for t in a for v in t));"
    "print(\"TT=\"+\",\".join(str(int(v)) for v in b))' 2>/dev/null";

static bool tables_from_python(int tri[TTRI][3], int cols[TTRI])
{
    FILE* f = popen(PY_CMD, "r");
    if (!f) return false;
    char l1[1200], l2[1200];
    bool ok = fgets(l1, sizeof l1, f) && fgets(l2, sizeof l2, f) &&
              !strncmp(l1, "TRI=", 4) && !strncmp(l2, "TT=", 3);
    pclose(f);
    if (!ok) return false;
    const char* p = l1 + 4;
    for (int t = 0; t < TTRI; ++t)
        for (int k = 0; k < 3; ++k) {
            char* end; long e = strtol(p, &end, 10);
            if (end == p || e < 0 || e > 11) return false;
            tri[t][k] = (int)e; p = end; if (*p == ',') ++p;
        }
    p = l2 + 3;
    long prev = -1;
    for (int k = 0; k < TTRI; ++k) {
        char* end; long v = strtol(p, &end, 10);
        if (end == p || v <= prev || v >= TFULL) return false;
        cols[k] = (int)v; prev = v; p = end; if (*p == ',') ++p;
    }
    return true;
}

// ---- fallback RNG (SeedSequence(0)+PCG64, Lemire draws everywhere) ----
static void tables_fallback(int tri[TTRI][3], int cols[TTRI])
{
    uint32_t hc = 0x43b0d7e5u;
    auto hashmix = [&hc](uint32_t v) { v ^= hc; hc *= 0x931e8875u; v *= hc; v ^= v >> 16; return v; };
    auto mixf = [](uint32_t a, uint32_t b) { uint32_t r = a*0xca01f9ddu - b*0x4973f715u; return r ^ (r >> 16); };
    uint32_t pool[4];
    for (int i = 0; i < 4; ++i) pool[i] = hashmix(0u);
    for (int s = 0; s < 4; ++s) for (int d2 = 0; d2 < 4; ++d2)
        if (s != d2) pool[d2] = mixf(pool[d2], hashmix(pool[s]));
    uint32_t hb = 0x8b51f9ddu, w[8];
    for (int i = 0; i < 8; ++i) {
        uint32_t v = pool[i % 4]; v ^= hb; hb *= 0x58f38dedu; v *= hb; v ^= v >> 16; w[i] = v;
    }
    uint64_t u64s[4];
    for (int k = 0; k < 4; ++k) u64s[k] = (uint64_t)w[2*k] | ((uint64_t)w[2*k+1] << 32);
    const __uint128_t MULT = ((__uint128_t)0x2360ed051fc65da4ULL << 64) | 0x4385df649fccf645ULL;
    __uint128_t inc = ((((__uint128_t)u64s[2] << 64) | u64s[3]) << 1) | 1;
    __uint128_t state = 0;
    state = state * MULT + inc;
    state += ((__uint128_t)u64s[0] << 64) | u64s[1];
    state = state * MULT + inc;
    bool has32 = false; uint32_t buf32 = 0;
    auto next32 = [&]() -> uint32_t {
        if (has32) { has32 = false; return buf32; }
        state = state * MULT + inc;
        uint64_t hi = (uint64_t)(state >> 64), lo = (uint64_t)state;
        unsigned rot = (unsigned)(hi >> 58);
        uint64_t v = hi ^ lo;
        uint64_t n = (v >> rot) | (v << ((64u - rot) & 63u));
        has32 = true; buf32 = (uint32_t)(n >> 32);
        return (uint32_t)n;
    };
    auto lemire = [&](uint32_t rng) -> uint32_t {
        if (rng == 0) return 0;
        uint32_t re = rng + 1u;
        uint64_t m = (uint64_t)next32() * re;
        uint32_t left = (uint32_t)m;
        if (left < re) {
            uint32_t thr = (0xFFFFFFFFu - rng) % re;
            while (left < thr) { m = (uint64_t)next32() * re; left = (uint32_t)m; }
        }
        return (uint32_t)(m >> 32);
    };
    auto choice = [&](int pop, int size, int64_t* out) {
        uint64_t ss = (uint64_t)(1.2 * (double)size), mask = ss;
        mask|=mask>>1; mask|=mask>>2; mask|=mask>>4; mask|=mask>>8; mask|=mask>>16; mask|=mask>>32;
        int set_size = (int)(mask + 1);
        uint64_t hs[128];
        for (int i = 0; i < set_size; ++i) hs[i] = ~0ULL;
        int k = 0;
        for (int j = pop - size; j < pop; ++j, ++k) {
            uint64_t val = lemire((uint32_t)j);
            uint64_t loc = val & mask;
            while (hs[loc] != ~0ULL && hs[loc] != val) loc = (loc + 1) & mask;
            if (hs[loc] == ~0ULL) { hs[loc] = val; out[k] = (int64_t)val; }
            else {
                loc = (uint64_t)j & mask;
                while (hs[loc] != ~0ULL) loc = (loc + 1) & mask;
                hs[loc] = (uint64_t)j; out[k] = j;
            }
        }
        for (int i = size - 1; i >= 1; --i) {
            uint32_t j = lemire((uint32_t)i);
            int64_t t = out[i]; out[i] = out[j]; out[j] = t;
        }
    };
    int64_t tmp[TTRI];
    for (int t = 0; t < TTRI; ++t) {
        choice(12, 3, tmp);
        tri[t][0] = (int)tmp[0]; tri[t][1] = (int)tmp[1]; tri[t][2] = (int)tmp[2];
    }
    choice(TFULL, TTRI, tmp);
    for (int i = 1; i < TTRI; ++i) {
        int64_t key = tmp[i]; int j = i - 1;
        while (j >= 0 && tmp[j] > key) { tmp[j+1] = tmp[j]; --j; }
        tmp[j+1] = key;
    }
    for (int k = 0; k < TTRI; ++k) cols[k] = (int)tmp[k];
}

// ---------------------------------------------------------------------------
extern "C" void kernel_launch(void* const* d_in, const int* in_sizes, int n_in,
                              void* d_out, int out_size)
{
    const float* d_offset = (const float*)d_in[0];
    const float* d_topo   = (const float*)d_in[1];
    float* out = (float*)d_out;

    int tri[TTRI][3], cols[TTRI];
    if (!tables_from_python(tri, cols)) {
        fprintf(stderr, "ATHENA: PYFAIL, using fallback RNG tables\n");
        tables_fallback(tri, cols);
    }
    static Params P;
    make_params(tri, cols, &P);

    k_field<<<NCELL / CPB, BT>>>(d_offset, d_topo, out, P);
    k_pair<<<NCELL / 256, 256>>>(out);
}

// round 7
// speedup vs baseline: 1.0134x; 1.0134x over previous
#include <cuda_runtime.h>
#include <cstdint>
#include <cstring>
#include <cstdio>
#include <cstdlib>

#define WC 48
#define NCELL (48*48*48)
#define TFULL 96
#define TTRI 48
#define OS_A 117649
#define OS_X 2401
#define OS_Y 49
#define BT 64                      // cells (threads) per block in k_field

// Per-triangle recipe: n = (c1 + d1*h1 + d0*g0) x (c2 + d2*h2 + d0*g0), g0 = -h0
// Packed as 4 float4 per triangle:
//   q0 = (c1x, c1y, c1z, c2x)
//   q1 = (c2y, c2z, g0x, g0y)
//   q2 = (g0z, h1x, h1y, h1z)
//   q3 = (h2x, h2y, h2z, bitcast(epk))
struct Params {
    float4   cf[TTRI * 4];
    uint32_t slotpack[24];    // col-group g: byte k = slot of col 4g+k (0xFF unused)
};

__device__ float4 g_sm[NCELL];

// ---------------------------------------------------------------------------
// k_field: one thread per cell; compact staging; coeffs in smem (no in-loop LDC)
// ---------------------------------------------------------------------------
__global__ __launch_bounds__(BT) void k_field(
    const float* __restrict__ off, const float* __restrict__ topo,
    float* __restrict__ out, Params P)
{
    __shared__ float    st[BT][49];    // 48 gathered topology cols (+pad)
    __shared__ float    sd[BT][13];    // 12 edge displacements (+pad)
    __shared__ float4   scf[TTRI * 4]; // coefficients (uniform LDS.128 broadcast)
    __shared__ uint32_t ssl[24];       // slot map

    const int tid   = threadIdx.x;
    const int cell0 = blockIdx.x * BT;

    #pragma unroll
    for (int i = tid; i < TTRI * 4; i += BT) scf[i] = P.cf[i];
    if (tid < 24) ssl[tid] = P.slotpack[tid];
    if (cell0 == 0 && tid == 0) out[0] = 0.0f;   // zero accumulator (pre-k_pair)

    // 12 edge displacements for this cell
    const int c = cell0 + tid;
    const int z = c % WC, y = (c / WC) % WC, x = c / (WC * WC);
    const float* ob = off + x * OS_X + y * OS_Y + z;
    sd[tid][0]  = ob[0];
    sd[tid][1]  = ob[OS_Y];
    sd[tid][2]  = ob[1];
    sd[tid][3]  = ob[OS_Y + 1];
    sd[tid][4]  = ob[OS_A];
    sd[tid][5]  = ob[OS_A + OS_X];
    sd[tid][6]  = ob[OS_A + 1];
    sd[tid][7]  = ob[OS_A + OS_X + 1];
    sd[tid][8]  = ob[2*OS_A];
    sd[tid][9]  = ob[2*OS_A + OS_X];
    sd[tid][10] = ob[2*OS_A + OS_Y];
    sd[tid][11] = ob[2*OS_A + OS_X + OS_Y];

    __syncthreads();   // ssl visible

    // stage topology: coalesced float4 loads, scatter needed lanes to slots
    const float4* t4 = reinterpret_cast<const float4*>(topo) + (size_t)cell0 * 24;
    #pragma unroll
    for (int it = 0; it < 24; ++it) {
        int i = tid + it * BT;           // [0, BT*24)
        float4 v = t4[i];
        int r = i / 24, g = i % 24;
        uint32_t sp = ssl[g];
        uint32_t s0 = sp & 0xffu, s1 = (sp >> 8) & 0xffu,
                 s2 = (sp >> 16) & 0xffu, s3 = sp >> 24;
        if (s0 != 0xffu) st[r][s0] = v.x;
        if (s1 != 0xffu) st[r][s1] = v.y;
        if (s2 != 0xffu) st[r][s2] = v.z;
        if (s3 != 0xffu) st[r][s3] = v.w;
    }

    __syncthreads();

    float s_ = 0.f, mx = 0.f, my = 0.f, mz = 0.f;
    const float* drow = sd[tid];
    const float* trow = st[tid];
    #pragma unroll 4
    for (int t = 0; t < TTRI; ++t) {
        float4 q0 = scf[t*4 + 0];
        float4 q1 = scf[t*4 + 1];
        float4 q2 = scf[t*4 + 2];
        float4 q3 = scf[t*4 + 3];
        uint32_t e = __float_as_uint(q3.w);
        float d0 = drow[e & 0xffu];
        float d1 = drow[(e >> 8) & 0xffu];
        float d2 = drow[(e >> 16) & 0xffu];
        float ax = fmaf(d1, q2.y, fmaf(d0, q1.z, q0.x));
        float ay = fmaf(d1, q2.z, fmaf(d0, q1.w, q0.y));
        float az = fmaf(d1, q2.w, fmaf(d0, q2.x, q0.z));
        float bx = fmaf(d2, q3.x, fmaf(d0, q1.z, q0.w));
        float by = fmaf(d2, q3.y, fmaf(d0, q1.w, q1.x));
        float bz = fmaf(d2, q3.z, fmaf(d0, q2.x, q1.y));
        float nx = fmaf(ay, bz, -az * by);
        float ny = fmaf(az, bx, -ax * bz);
        float nz = fmaf(ax, by, -ay * bx);
        float inv = rsqrtf(fmaf(nx, nx, fmaf(ny, ny, fmaf(nz, nz, 1e-8f))));
        float p = trow[t];                      // slot t == triangle t (sorted map)
        s_ += p;
        float w = p * inv;
        mx = fmaf(w, nx, mx); my = fmaf(w, ny, my); mz = fmaf(w, nz, mz);
    }
    g_sm[c] = make_float4(s_, mx, my, mz);
}

// ---------------------------------------------------------------------------
// k_pair: self + forward-neighbor terms; float atomic into out[0]
// ---------------------------------------------------------------------------
__global__ __launch_bounds__(256) void k_pair(float* __restrict__ out)
{
    int c = blockIdx.x * 256 + threadIdx.x;
    int z = c % WC, xy = c / WC, y = xy % WC, x = xy / WC;
    float4 a = g_sm[c];
    float acc = a.x*a.x - a.y*a.y - a.z*a.z - a.w*a.w;
    if (x < WC-1) { float4 b = g_sm[c + WC*WC]; acc += a.x*b.x - a.y*b.y - a.z*b.z - a.w*b.w; }
    if (y < WC-1) { float4 b = g_sm[c + WC];    acc += a.x*b.x - a.y*b.y - a.z*b.z - a.w*b.w; }
    if (z < WC-1) { float4 b = g_sm[c + 1];     acc += a.x*b.x - a.y*b.y - a.z*b.z - a.w*b.w; }
    acc *= 2.0f;
    #pragma unroll
    for (int o = 16; o > 0; o >>= 1) acc += __shfl_down_sync(0xffffffffu, acc, o);
    __shared__ float red[8];
    if ((threadIdx.x & 31) == 0) red[threadIdx.x >> 5] = acc;
    __syncthreads();
    if (threadIdx.x < 8) {
        float v = red[threadIdx.x];
        #pragma unroll
        for (int o = 4; o > 0; o >>= 1) v += __shfl_down_sync(0xffu, v, o);
        if (threadIdx.x == 0) atomicAdd(out, v);
    }
}

// ---------------------------------------------------------------------------
// HOST: geometry + params
// ---------------------------------------------------------------------------
static const int EC[12][3] = {{0,0,0},{0,1,0},{0,0,1},{0,1,1},
                              {0,0,0},{1,0,0},{0,0,1},{1,0,1},
                              {0,0,0},{1,0,0},{0,1,0},{1,1,0}};
static const int EA[12] = {0,0,0,0,1,1,1,1,2,2,2,2};

static void make_params(const int tri[TTRI][3], const int cols[TTRI], Params* P)
{
    for (int t = 0; t < TTRI; ++t) {
        int e0 = tri[t][0], e1 = tri[t][1], e2 = tri[t][2];
        float b0[3], b1[3], b2[3];
        for (int k = 0; k < 3; ++k) {
            b0[k] = EC[e0][k] + (k == EA[e0] ? 0.5f : 0.f);
            b1[k] = EC[e1][k] + (k == EA[e1] ? 0.5f : 0.f);
            b2[k] = EC[e2][k] + (k == EA[e2] ? 0.5f : 0.f);
        }
        float c1[3], c2[3], g0[3], h1[3], h2[3];
        for (int k = 0; k < 3; ++k) {
            c1[k] = b1[k] - b0[k];
            c2[k] = b2[k] - b0[k];
            g0[k] = -(float)(EA[e0] == k);
            h1[k] = (float)(EA[e1] == k);
            h2[k] = (float)(EA[e2] == k);
        }
        uint32_t epk = (uint32_t)e0 | ((uint32_t)e1 << 8) | ((uint32_t)e2 << 16);
        float epkf; memcpy(&epkf, &epk, 4);
        P->cf[t*4 + 0] = make_float4(c1[0], c1[1], c1[2], c2[0]);
        P->cf[t*4 + 1] = make_float4(c2[1], c2[2], g0[0], g0[1]);
        P->cf[t*4 + 2] = make_float4(g0[2], h1[0], h1[1], h1[2]);
        P->cf[t*4 + 3] = make_float4(h2[0], h2[1], h2[2], epkf);
    }
    for (int g = 0; g < 24; ++g) {
        uint32_t sp = 0;
        for (int k = 0; k < 4; ++k) {
            int col = 4*g + k, slot = 0xFF;
            for (int s = 0; s < TTRI; ++s) if (cols[s] == col) { slot = s; break; }
            sp |= (uint32_t)slot << (8*k);
        }
        P->slotpack[g] = sp;
    }
}

// ---- ground-truth tables from in-container python/numpy (verified working) ----
static const char* PY_CMD =
    "python3 -c 'import numpy as np;r=np.random.default_rng(0);"
    "a=[r.choice(12,size=3,replace=False) for _ in range(48)];"
    "b=np.sort(r.choice(96,size=48,replace=False));"
    "print(\"TRI=\"+\",\".join(str(int(v)) for t in a for v in t));"
    "print(\"TT=\"+\",\".join(str(int(v)) for v in b))' 2>/dev/null";

static bool tables_from_python(int tri[TTRI][3], int cols[TTRI])
{
    FILE* f = popen(PY_CMD, "r");
    if (!f) return false;
    char l1[1200], l2[1200];
    bool ok = fgets(l1, sizeof l1, f) && fgets(l2, sizeof l2, f) &&
              !strncmp(l1, "TRI=", 4) && !strncmp(l2, "TT=", 3);
    pclose(f);
    if (!ok) return false;
    const char* p = l1 + 4;
    for (int t = 0; t < TTRI; ++t)
        for (int k = 0; k < 3; ++k) {
            char* end; long e = strtol(p, &end, 10);
            if (end == p || e < 0 || e > 11) return false;
            tri[t][k] = (int)e; p = end; if (*p == ',') ++p;
        }
    p = l2 + 3;
    long prev = -1;
    for (int k = 0; k < TTRI; ++k) {
        char* end; long v = strtol(p, &end, 10);
        if (end == p || v <= prev || v >= TFULL) return false;
        cols[k] = (int)v; prev = v; p = end; if (*p == ',') ++p;
    }
    return true;
}

// ---- fallback RNG (SeedSequence(0)+PCG64, Lemire draws everywhere) ----
static void tables_fallback(int tri[TTRI][3], int cols[TTRI])
{
    uint32_t hc = 0x43b0d7e5u;
    auto hashmix = [&hc](uint32_t v) { v ^= hc; hc *= 0x931e8875u; v *= hc; v ^= v >> 16; return v; };
    auto mixf = [](uint32_t a, uint32_t b) { uint32_t r = a*0xca01f9ddu - b*0x4973f715u; return r ^ (r >> 16); };
    uint32_t pool[4];
    for (int i = 0; i < 4; ++i) pool[i] = hashmix(0u);
    for (int s = 0; s < 4; ++s) for (int d2 = 0; d2 < 4; ++d2)
        if (s != d2) pool[d2] = mixf(pool[d2], hashmix(pool[s]));
    uint32_t hb = 0x8b51f9ddu, w[8];
    for (int i = 0; i < 8; ++i) {
        uint32_t v = pool[i % 4]; v ^= hb; hb *= 0x58f38dedu; v *= hb; v ^= v >> 16; w[i] = v;
    }
    uint64_t u64s[4];
    for (int k = 0; k < 4; ++k) u64s[k] = (uint64_t)w[2*k] | ((uint64_t)w[2*k+1] << 32);
    const __uint128_t MULT = ((__uint128_t)0x2360ed051fc65da4ULL << 64) | 0x4385df649fccf645ULL;
    __uint128_t inc = ((((__uint128_t)u64s[2] << 64) | u64s[3]) << 1) | 1;
    __uint128_t state = 0;
    state = state * MULT + inc;
    state += ((__uint128_t)u64s[0] << 64) | u64s[1];
    state = state * MULT + inc;
    bool has32 = false; uint32_t buf32 = 0;
    auto next32 = [&]() -> uint32_t {
        if (has32) { has32 = false; return buf32; }
        state = state * MULT + inc;
        uint64_t hi = (uint64_t)(state >> 64), lo = (uint64_t)state;
        unsigned rot = (unsigned)(hi >> 58);
        uint64_t v = hi ^ lo;
        uint64_t n = (v >> rot) | (v << ((64u - rot) & 63u));
        has32 = true; buf32 = (uint32_t)(n >> 32);
        return (uint32_t)n;
    };
    auto lemire = [&](uint32_t rng) -> uint32_t {
        if (rng == 0) return 0;
        uint32_t re = rng + 1u;
        uint64_t m = (uint64_t)next32() * re;
        uint32_t left = (uint32_t)m;
        if (left < re) {
            uint32_t thr = (0xFFFFFFFFu - rng) % re;
            while (left < thr) { m = (uint64_t)next32() * re; left = (uint32_t)m; }
        }
        return (uint32_t)(m >> 32);
    };
    auto choice = [&](int pop, int size, int64_t* out) {
        uint64_t ss = (uint64_t)(1.2 * (double)size), mask = ss;
        mask|=mask>>1; mask|=mask>>2; mask|=mask>>4; mask|=mask>>8; mask|=mask>>16; mask|=mask>>32;
        int set_size = (int)(mask + 1);
        uint64_t hs[128];
        for (int i = 0; i < set_size; ++i) hs[i] = ~0ULL;
        int k = 0;
        for (int j = pop - size; j < pop; ++j, ++k) {
            uint64_t val = lemire((uint32_t)j);
            uint64_t loc = val & mask;
            while (hs[loc] != ~0ULL && hs[loc] != val) loc = (loc + 1) & mask;
            if (hs[loc] == ~0ULL) { hs[loc] = val; out[k] = (int64_t)val; }
            else {
                loc = (uint64_t)j & mask;
                while (hs[loc] != ~0ULL) loc = (loc + 1) & mask;
                hs[loc] = (uint64_t)j; out[k] = j;
            }
        }
        for (int i = size - 1; i >= 1; --i) {
            uint32_t j = lemire((uint32_t)i);
            int64_t t = out[i]; out[i] = out[j]; out[j] = t;
        }
    };
    int64_t tmp[TTRI];
    for (int t = 0; t < TTRI; ++t) {
        choice(12, 3, tmp);
        tri[t][0] = (int)tmp[0]; tri[t][1] = (int)tmp[1]; tri[t][2] = (int)tmp[2];
    }
    choice(TFULL, TTRI, tmp);
    for (int i = 1; i < TTRI; ++i) {
        int64_t key = tmp[i]; int j = i - 1;
        while (j >= 0 && tmp[j] > key) { tmp[j+1] = tmp[j]; --j; }
        tmp[j+1] = key;
    }
    for (int k = 0; k < TTRI; ++k) cols[k] = (int)tmp[k];
}

// ---------------------------------------------------------------------------
extern "C" void kernel_launch(void* const* d_in, const int* in_sizes, int n_in,
                              void* d_out, int out_size)
{
    const float* d_offset = (const float*)d_in[0];
    const float* d_topo   = (const float*)d_in[1];
    float* out = (float*)d_out;

    int tri[TTRI][3], cols[TTRI];
    if (!tables_from_python(tri, cols)) {
        fprintf(stderr, "ATHENA: PYFAIL, using fallback RNG tables\n");
        tables_fallback(tri, cols);
    }
    static Params P;
    make_params(tri, cols, &P);

    k_field<<<NCELL / BT, BT>>>(d_offset, d_topo, out, P);
    k_pair<<<NCELL / 256, 256>>>(out);
}